// round 14
// baseline (speedup 1.0000x reference)
#include <cuda_runtime.h>
#include <cuda_fp16.h>
#include <math.h>

// Problem constants
#define B_   2
#define S_   2048
#define D_   1024
#define H_   16
#define DK_  64
#define M_   (B_*S_)     // 4096
#define NQKV (3*D_)      // 3072

// Scratch (device globals — no allocation allowed)
__device__ __half  g_Q[B_*H_*S_*DK_];             // [bh][s][d], pre-scaled by log2e/8
__device__ __half  g_K[B_*H_*S_*DK_];             // [bh][s][d]
__device__ __half  g_V[B_*H_*S_*DK_];             // [bh][d][s]  (transposed)
__device__ __half  g_attn[(size_t)M_*D_];
__device__ __half  g_xh[(size_t)M_*D_];
__device__ __half  g_wqkvh[(size_t)NQKV*D_];
__device__ __half  g_woh[(size_t)D_*D_];
__device__ float2  g_rope[2048*32];               // [pos][pair] = (cos, sin)

// ---------------- helpers ----------------
__device__ __forceinline__ void mma_f16(float* c, const unsigned* a, const unsigned* b) {
    asm volatile(
        "mma.sync.aligned.m16n8k16.row.col.f32.f16.f16.f32 "
        "{%0,%1,%2,%3}, {%4,%5,%6,%7}, {%8,%9}, {%0,%1,%2,%3};\n"
        : "+f"(c[0]), "+f"(c[1]), "+f"(c[2]), "+f"(c[3])
        : "r"(a[0]), "r"(a[1]), "r"(a[2]), "r"(a[3]),
          "r"(b[0]), "r"(b[1]));
}

__device__ __forceinline__ void ldmx4(unsigned& r0, unsigned& r1, unsigned& r2, unsigned& r3,
                                      unsigned addr) {
    asm volatile("ldmatrix.sync.aligned.m8n8.x4.shared.b16 {%0,%1,%2,%3}, [%4];\n"
        : "=r"(r0), "=r"(r1), "=r"(r2), "=r"(r3) : "r"(addr));
}

__device__ __forceinline__ void cp16(unsigned saddr, const void* gaddr) {
    asm volatile("cp.async.cg.shared.global [%0], [%1], 16;\n" :: "r"(saddr), "l"(gaddr));
}
__device__ __forceinline__ void cp_commit() { asm volatile("cp.async.commit_group;\n"); }
template<int N> __device__ __forceinline__ void cp_wait() {
    asm volatile("cp.async.wait_group %0;\n" :: "n"(N));
}
__device__ __forceinline__ unsigned pack2(float lo, float hi) {
    __half2 h = __floats2half2_rn(lo, hi);
    return *(unsigned*)&h;
}
__device__ __forceinline__ unsigned ex2_h2(unsigned s) {
    unsigned r;
    asm("ex2.approx.f16x2 %0, %1;" : "=r"(r) : "r"(s));
    return r;
}

// ---------------- fused init: fp32->fp16 (x, Wqkv, Wo) + RoPE table ----------------
#define N8_X   (M_*D_/8)
#define N8_WQ  (NQKV*D_/8)
#define N8_WO  (D_*D_/8)
#define N8_ALL (N8_X + N8_WQ + N8_WO)

__global__ void init_all_kernel(const float4* __restrict__ x,
                                const float4* __restrict__ wq,
                                const float4* __restrict__ wo)
{
    if (blockIdx.x < 256) {
        int i = blockIdx.x * 256 + threadIdx.x;
        int p = i & 31, posv = i >> 5;
        float freq = exp2f(-(float)p * (13.287712379549449f / 32.0f));
        float ang = (float)posv * freq;
        float sn, cs;
        sincosf(ang, &sn, &cs);
        g_rope[i] = make_float2(cs, sn);
    }
    __half* xh  = g_xh;
    __half* wqh = g_wqkvh;
    __half* woh = g_woh;
    for (int i = blockIdx.x * 256 + threadIdx.x; i < N8_ALL; i += gridDim.x * 256) {
        const float4* s; uint4* d; int j = i;
        if (j < N8_X)            { s = x  + 2*j;              d = (uint4*)xh  + j; }
        else if ((j -= N8_X) < N8_WQ) { s = wq + 2*j;         d = (uint4*)wqh + j; }
        else { j -= N8_WQ;         s = wo + 2*j;              d = (uint4*)woh + j; }
        float4 a = s[0], b = s[1];
        uint4 o;
        o.x = pack2(a.x, a.y); o.y = pack2(a.z, a.w);
        o.z = pack2(b.x, b.y); o.w = pack2(b.z, b.w);
        *d = o;
    }
}

// ============================================================
// fp16 GEMM: block 128x128, BK=32 halves per stage, 4 stages,
// PAIR-processed mainloop: one wait+sync+commit per 2 ktiles.
// 256 threads, 8 warps (2m x 4n), warp 64x32, ldmatrix.
// ============================================================
#define LDAH 40              // smem row stride (halves): 32 + 8 pad
#define STGH (128*LDAH)      // halves per stage per matrix = 5120
#define GST  4               // stages (2 pairs)
#define NPAIR 16             // K=1024 / 64

__device__ __forceinline__ void gemm_load_stage(
    __half* Asb, __half* Bsb, const __half* A, const __half* W,
    int m0, int n0, int k0, int tid)
{
    int row = tid >> 1;
    int cp  = (tid & 1) * 2;    // chunks cp, cp+1 (of 4 per 64B row)
    unsigned sa = (unsigned)__cvta_generic_to_shared(Asb + row*LDAH + cp*8);
    unsigned sb = (unsigned)__cvta_generic_to_shared(Bsb + row*LDAH + cp*8);
    const __half* ga = A + (size_t)(m0 + row)*1024 + k0 + cp*8;
    const __half* gb = W + (size_t)(n0 + row)*1024 + k0 + cp*8;
    cp16(sa,      ga);
    cp16(sa + 16, ga + 8);
    cp16(sb,      gb);
    cp16(sb + 16, gb + 8);
}

// Q pre-scale: 1/sqrt(64) * log2(e) so attention can use raw exp2
#define QSCALE (0.125f * 1.4426950408889634f)

template<bool ROPE>
__global__ __launch_bounds__(256)
void gemm_f16(const __half* __restrict__ A, const __half* __restrict__ W,
              const int* __restrict__ pos, float* __restrict__ Cout)
{
    extern __shared__ __half hsm[];
    __half* As = hsm;            // GST stages x 5120
    __half* Bs = hsm + GST*STGH;

    const int tid = threadIdx.x, lane = tid & 31, wrp = tid >> 5;
    const int wm = wrp >> 2, wn = wrp & 3;
    const int g  = lane >> 2, tg = lane & 3;
    const int m0 = blockIdx.y * 128, n0 = blockIdx.x * 128;

    const int a_off = (wm*64 + (lane & 15))*LDAH + ((lane >> 4) << 3);
    const int b_off = (wn*32 + (lane & 7) + ((lane & 16) >> 1))*LDAH + (lane & 8);
    const unsigned sa_base = (unsigned)__cvta_generic_to_shared(As) + a_off*2;
    const unsigned sb_base = (unsigned)__cvta_generic_to_shared(Bs) + b_off*2;

    float acc[4][4][4];
    #pragma unroll
    for (int i = 0; i < 4; i++)
        #pragma unroll
        for (int j = 0; j < 4; j++)
            #pragma unroll
            for (int k = 0; k < 4; k++) acc[i][j][k] = 0.f;

    // prologue: pair 0 -> stages 0,1
    gemm_load_stage(As,        Bs,        A, W, m0, n0, 0,  tid);
    gemm_load_stage(As + STGH, Bs + STGH, A, W, m0, n0, 32, tid);
    cp_commit();

    for (int p = 0; p < NPAIR; p++) {
        cp_wait<0>();
        __syncthreads();
        if (p + 1 < NPAIR) {
            int sb = ((p + 1) & 1) * 2;
            gemm_load_stage(As + sb*STGH,     Bs + sb*STGH,     A, W, m0, n0, (p+1)*64,      tid);
            gemm_load_stage(As + (sb+1)*STGH, Bs + (sb+1)*STGH, A, W, m0, n0, (p+1)*64 + 32, tid);
        }
        cp_commit();

        #pragma unroll
        for (int half = 0; half < 2; half++) {
            const int st = (p & 1)*2 + half;
            const unsigned sa = sa_base + st*STGH*2;
            const unsigned sb2 = sb_base + st*STGH*2;
            #pragma unroll
            for (int ks = 0; ks < 2; ks++) {
                unsigned af[4][4], bf[4][2];
                #pragma unroll
                for (int mt = 0; mt < 4; mt++)
                    ldmx4(af[mt][0], af[mt][1], af[mt][2], af[mt][3],
                          sa + (mt*16*LDAH + ks*16)*2);
                #pragma unroll
                for (int q = 0; q < 2; q++)
                    ldmx4(bf[2*q][0], bf[2*q][1], bf[2*q+1][0], bf[2*q+1][1],
                          sb2 + (q*16*LDAH + ks*16)*2);
                #pragma unroll
                for (int mt = 0; mt < 4; mt++)
                    #pragma unroll
                    for (int nt = 0; nt < 4; nt++)
                        mma_f16(acc[mt][nt], af[mt], bf[nt]);
            }
        }
    }

    // ---- epilogue ----
    if (ROPE) {
        const int baseN = n0 + wn*32;
        const int which = baseN >> 10;              // 0:Q 1:K 2:V
        const int h     = (baseN & 1023) >> 6;
        const int dd0   = baseN & 63;               // 0 or 32
        const float qs  = (which == 0) ? QSCALE : 1.0f;
        #pragma unroll
        for (int mt = 0; mt < 4; mt++) {
            int r0 = m0 + wm*64 + mt*16 + g;
            int r1 = r0 + 8;
            int b0i = r0 >> 11, s0 = r0 & 2047;
            int b1i = r1 >> 11, s1 = r1 & 2047;
            if (which == 2) {
                // transposed V: [bh][d][s]
                const size_t base0 = (size_t)(b0i*H_ + h)*DK_;
                const size_t base1 = (size_t)(b1i*H_ + h)*DK_;
                #pragma unroll
                for (int nt = 0; nt < 4; nt++) {
                    int dd = dd0 + nt*8 + 2*tg;
                    g_V[(base0 + dd    )*S_ + s0] = __float2half_rn(acc[mt][nt][0]);
                    g_V[(base0 + dd + 1)*S_ + s0] = __float2half_rn(acc[mt][nt][1]);
                    g_V[(base1 + dd    )*S_ + s1] = __float2half_rn(acc[mt][nt][2]);
                    g_V[(base1 + dd + 1)*S_ + s1] = __float2half_rn(acc[mt][nt][3]);
                }
            } else {
                __half* gq = (which == 0) ? g_Q : g_K;
                int p0 = pos[r0], p1 = pos[r1];
                __half* d0 = gq + ((size_t)((b0i*H_ + h)*S_ + s0))*DK_;
                __half* d1 = gq + ((size_t)((b1i*H_ + h)*S_ + s1))*DK_;
                #pragma unroll
                for (int nt = 0; nt < 4; nt++) {
                    int dd = dd0 + nt*8 + 2*tg;
                    int pp = dd >> 1;
                    float2 cs0 = g_rope[p0*32 + pp];
                    float2 cs1 = g_rope[p1*32 + pp];
                    float e0 = acc[mt][nt][0], o0 = acc[mt][nt][1];
                    float e1 = acc[mt][nt][2], o1 = acc[mt][nt][3];
                    *(unsigned*)(d0 + dd) = pack2(qs*(cs0.x*e0 - cs0.y*o0), qs*(cs0.y*e0 + cs0.x*o0));
                    *(unsigned*)(d1 + dd) = pack2(qs*(cs1.x*e1 - cs1.y*o1), qs*(cs1.y*e1 + cs1.x*o1));
                }
            }
        }
    } else {
        #pragma unroll
        for (int mt = 0; mt < 4; mt++) {
            int r0 = m0 + wm*64 + mt*16 + g;
            #pragma unroll
            for (int nt = 0; nt < 4; nt++) {
                int col = n0 + wn*32 + nt*8 + 2*tg;
                *(float2*)(Cout + (size_t)r0*1024 + col)     = make_float2(acc[mt][nt][0], acc[mt][nt][1]);
                *(float2*)(Cout + (size_t)(r0+8)*1024 + col) = make_float2(acc[mt][nt][2], acc[mt][nt][3]);
            }
        }
    }
}

// ============================================================
// Flash attention (R12): fp16 mma, 3-stage cp.async, ldmatrix,
// log2 softmax via ex2.approx.f16x2, row-sum via ones-column mma.
// Block: 128 q-rows, 8 warps (16 rows each). Key tiles of 64.
// V in transposed [bh][d][s] layout -> plain ldmatrix B-fragments.
// ============================================================
#define ABM 128
#define ABN 64
#define KSH 72               // K/V smem row stride (halves)
#define KVSH (ABN*KSH)       // 4608 halves per matrix per stage
#define NSTG 3

__device__ __forceinline__ void load_kv(__half* Kd, __half* Vd,
    const __half* Kp, const __half* Vtp, int n0, int tid)
{
    int row = tid >> 2;           // 0..63
    int ch  = (tid & 3) * 2;      // chunks ch, ch+1 (of 8 per 128B row)
    const __half* kg = Kp  + (size_t)(n0 + row)*DK_ + ch*8;
    const __half* vg = Vtp + (size_t)row*S_ + n0 + ch*8;
    unsigned ks = (unsigned)__cvta_generic_to_shared(Kd + row*KSH + ch*8);
    unsigned vs = (unsigned)__cvta_generic_to_shared(Vd + row*KSH + ch*8);
    cp16(ks,      kg);
    cp16(ks + 16, kg + 8);
    cp16(vs,      vg);
    cp16(vs + 16, vg + 8);
}

__global__ __launch_bounds__(256)
void attn_mma_kernel()
{
    extern __shared__ __half hsm[];   // NSTG stages x (K 4608 + V 4608) halves

    const int tid = threadIdx.x, lane = tid & 31, w = tid >> 5;
    const int g = lane >> 2, tg = lane & 3;
    const int bh = blockIdx.y;
    const int tile = (int)gridDim.x - 1 - (int)blockIdx.x;   // heavy tiles first
    const int m0 = tile * ABM;

    const __half* Qp  = g_Q + (size_t)bh * S_ * DK_;
    const __half* Kp  = g_K + (size_t)bh * S_ * DK_;
    const __half* Vtp = g_V + (size_t)bh * DK_ * S_;

    const int row0 = m0 + w*16 + g;
    const int row1 = row0 + 8;

    const int kv_off = ((lane & 7) + ((lane & 16) >> 1))*KSH + (lane & 8);
    const unsigned smem_base = (unsigned)__cvta_generic_to_shared(hsm) + kv_off*2;

    // ones-column B fragment for the row-sum mma: B[n][k] = (n==0)
    const unsigned ones_b = ((lane >> 2) == 0) ? 0x3C003C00u : 0u;
    unsigned ones_bb[2] = { ones_b, ones_b };

    // ---- Q fragments straight from gmem (one-time, pre-scaled) ----
    unsigned qa[4][4];
    {
        const __half* q0 = Qp + (size_t)row0*DK_ + 2*tg;
        const __half* q1 = Qp + (size_t)row1*DK_ + 2*tg;
        #pragma unroll
        for (int ks = 0; ks < 4; ks++) {
            qa[ks][0] = *(const unsigned*)(q0 + ks*16);
            qa[ks][1] = *(const unsigned*)(q1 + ks*16);
            qa[ks][2] = *(const unsigned*)(q0 + ks*16 + 8);
            qa[ks][3] = *(const unsigned*)(q1 + ks*16 + 8);
        }
    }

    float o[8][4];
    #pragma unroll
    for (int nt = 0; nt < 8; nt++)
        #pragma unroll
        for (int i = 0; i < 4; i++) o[nt][i] = 0.f;
    float osum[4] = {0.f, 0.f, 0.f, 0.f};     // row-sum accumulator (ones column)

    float mrow0 = -1e30f, mrow1 = -1e30f;
    const int fullT = m0 / ABN;
    const int nT = fullT + 2;

    load_kv(hsm, hsm + KVSH, Kp, Vtp, 0, tid);
    cp_commit();
    if (1 < nT) {
        __half* st = hsm + 2*KVSH;
        load_kv(st, st + KVSH, Kp, Vtp, ABN, tid);
    }
    cp_commit();

    for (int t = 0; t < nT; t++) {
        cp_wait<1>();
        __syncthreads();
        if (t + 2 < nT) {
            __half* st = hsm + ((t + 2) % NSTG) * 2 * KVSH;
            load_kv(st, st + KVSH, Kp, Vtp, (t + 2)*ABN, tid);
        }
        cp_commit();

        const unsigned Ksb = smem_base + ((t % NSTG) * 2 * KVSH)*2;
        const unsigned Vsb = Ksb + KVSH*2;
        const int n0 = t * ABN;

        // ---- scores: S = Q @ K^T  (log2-domain; scale folded into Q) ----
        float sc[8][4];
        #pragma unroll
        for (int nt = 0; nt < 8; nt++)
            #pragma unroll
            for (int i = 0; i < 4; i++) sc[nt][i] = 0.f;

        #pragma unroll
        for (int ks = 0; ks < 4; ks++) {
            #pragma unroll
            for (int p = 0; p < 4; p++) {
                unsigned bf[2][2];
                ldmx4(bf[0][0], bf[0][1], bf[1][0], bf[1][1],
                      Ksb + (p*16*KSH + ks*16)*2);
                mma_f16(sc[2*p],   qa[ks], bf[0]);
                mma_f16(sc[2*p+1], qa[ks], bf[1]);
            }
        }

        // causal mask (only the last two tiles touch the diagonal)
        if (t >= fullT) {
            #pragma unroll
            for (int nt = 0; nt < 8; nt++) {
                int c0 = n0 + nt*8 + 2*tg, c1 = c0 + 1;
                if (c0 > row0) sc[nt][0] = -1e30f;
                if (c1 > row0) sc[nt][1] = -1e30f;
                if (c0 > row1) sc[nt][2] = -1e30f;
                if (c1 > row1) sc[nt][3] = -1e30f;
            }
        }

        // ---- running max (log2 domain) ----
        float mx0 = -1e30f, mx1 = -1e30f;
        #pragma unroll
        for (int nt = 0; nt < 8; nt++) {
            mx0 = fmaxf(mx0, fmaxf(sc[nt][0], sc[nt][1]));
            mx1 = fmaxf(mx1, fmaxf(sc[nt][2], sc[nt][3]));
        }
        mx0 = fmaxf(mx0, __shfl_xor_sync(0xffffffffu, mx0, 1));
        mx0 = fmaxf(mx0, __shfl_xor_sync(0xffffffffu, mx0, 2));
        mx1 = fmaxf(mx1, __shfl_xor_sync(0xffffffffu, mx1, 1));
        mx1 = fmaxf(mx1, __shfl_xor_sync(0xffffffffu, mx1, 2));

        float mn0 = fmaxf(mrow0, mx0), mn1 = fmaxf(mrow1, mx1);
        float al0 = exp2f(mrow0 - mn0), al1 = exp2f(mrow1 - mn1);
        mrow0 = mn0; mrow1 = mn1;

        // ---- P = 2^(s-m) directly in packed fp16 (A-fragment layout) ----
        unsigned pP[4][4];
        #pragma unroll
        for (int ks = 0; ks < 4; ks++) {
            pP[ks][0] = ex2_h2(pack2(sc[2*ks  ][0] - mn0, sc[2*ks  ][1] - mn0));
            pP[ks][1] = ex2_h2(pack2(sc[2*ks  ][2] - mn1, sc[2*ks  ][3] - mn1));
            pP[ks][2] = ex2_h2(pack2(sc[2*ks+1][0] - mn0, sc[2*ks+1][1] - mn0));
            pP[ks][3] = ex2_h2(pack2(sc[2*ks+1][2] - mn1, sc[2*ks+1][3] - mn1));
        }

        // rescale O and row-sum accumulator
        #pragma unroll
        for (int nt = 0; nt < 8; nt++) {
            o[nt][0] *= al0; o[nt][1] *= al0;
            o[nt][2] *= al1; o[nt][3] *= al1;
        }
        osum[0] *= al0; osum[1] *= al0;
        osum[2] *= al1; osum[3] *= al1;

        // ---- PV + row-sum mma ----
        #pragma unroll
        for (int ks = 0; ks < 4; ks++) {
            mma_f16(osum, pP[ks], ones_bb);
            #pragma unroll
            for (int p = 0; p < 4; p++) {
                unsigned bf[2][2];
                ldmx4(bf[0][0], bf[0][1], bf[1][0], bf[1][1],
                      Vsb + (p*16*KSH + ks*16)*2);
                mma_f16(o[2*p],   pP[ks], bf[0]);
                mma_f16(o[2*p+1], pP[ks], bf[1]);
            }
        }
    }

    // ---- epilogue: recover l via shfl, normalize, write fp16 ----
    float l0 = __shfl_sync(0xffffffffu, osum[0], lane & ~3);
    float l1 = __shfl_sync(0xffffffffu, osum[2], lane & ~3);
    const float il0 = 1.0f / l0, il1 = 1.0f / l1;
    const int bb = bh >> 4, hh = bh & 15;
    __half* dst0 = g_attn + ((size_t)(bb*S_ + row0))*D_ + hh*DK_;
    __half* dst1 = g_attn + ((size_t)(bb*S_ + row1))*D_ + hh*DK_;
    #pragma unroll
    for (int nt = 0; nt < 8; nt++) {
        int d = nt*8 + 2*tg;
        *(unsigned*)(dst0 + d) = pack2(o[nt][0]*il0, o[nt][1]*il0);
        *(unsigned*)(dst1 + d) = pack2(o[nt][2]*il1, o[nt][3]*il1);
    }
}

// ============================================================
// Launch
// ============================================================
extern "C" void kernel_launch(void* const* d_in, const int* in_sizes, int n_in,
                              void* d_out, int out_size)
{
    const float* x    = (const float*)d_in[0];
    const int*   pos  = (const int*)  d_in[1];
    const float* wqkv = (const float*)d_in[2];
    const float* wo   = (const float*)d_in[3];
    float* out = (float*)d_out;

    (void)in_sizes; (void)n_in; (void)out_size;

    const int GEMM_SMEM = GST*STGH*2*(int)sizeof(__half);      // 81920
    const int ATTN_SMEM = NSTG*2*KVSH*(int)sizeof(__half);     // 55296
    cudaFuncSetAttribute((const void*)gemm_f16<true>,
                         cudaFuncAttributeMaxDynamicSharedMemorySize, GEMM_SMEM);
    cudaFuncSetAttribute((const void*)gemm_f16<false>,
                         cudaFuncAttributeMaxDynamicSharedMemorySize, GEMM_SMEM);
    cudaFuncSetAttribute((const void*)attn_mma_kernel,
                         cudaFuncAttributeMaxDynamicSharedMemorySize, ATTN_SMEM);

    __half* xh; __half* wqh; __half* woh; __half* ah;
    cudaGetSymbolAddress((void**)&xh,  g_xh);
    cudaGetSymbolAddress((void**)&wqh, g_wqkvh);
    cudaGetSymbolAddress((void**)&woh, g_woh);
    cudaGetSymbolAddress((void**)&ah,  g_attn);

    init_all_kernel<<<888, 256>>>((const float4*)x, (const float4*)wqkv, (const float4*)wo);

    gemm_f16<true ><<<dim3(NQKV/128, M_/128), 256, GEMM_SMEM>>>(xh, wqh, pos, nullptr);
    attn_mma_kernel<<<dim3(S_/ABM, B_*H_), 256, ATTN_SMEM>>>();
    gemm_f16<false><<<dim3(D_/128, M_/128), 256, GEMM_SMEM>>>(ah, woh, pos, out);
}

// round 15
// speedup vs baseline: 1.1106x; 1.1106x over previous
#include <cuda_runtime.h>
#include <cuda_fp16.h>
#include <math.h>

// Problem constants
#define B_   2
#define S_   2048
#define D_   1024
#define H_   16
#define DK_  64
#define M_   (B_*S_)     // 4096
#define NQKV (3*D_)      // 3072

// Scratch (device globals — no allocation allowed)
__device__ __half  g_Q[B_*H_*S_*DK_];             // [bh][s][d], pre-scaled by log2e/8
__device__ __half  g_K[B_*H_*S_*DK_];             // [bh][s][d]
__device__ __half  g_V[B_*H_*S_*DK_];             // [bh][d][s]  (transposed)
__device__ __half  g_attn[(size_t)M_*D_];
__device__ __half  g_xh[(size_t)M_*D_];
__device__ __half  g_wqkvh[(size_t)NQKV*D_];
__device__ __half  g_woh[(size_t)D_*D_];
__device__ float2  g_rope[2048*32];               // [pos][pair] = (cos, sin)

// ---------------- helpers ----------------
__device__ __forceinline__ void mma_f16(float* c, const unsigned* a, const unsigned* b) {
    asm volatile(
        "mma.sync.aligned.m16n8k16.row.col.f32.f16.f16.f32 "
        "{%0,%1,%2,%3}, {%4,%5,%6,%7}, {%8,%9}, {%0,%1,%2,%3};\n"
        : "+f"(c[0]), "+f"(c[1]), "+f"(c[2]), "+f"(c[3])
        : "r"(a[0]), "r"(a[1]), "r"(a[2]), "r"(a[3]),
          "r"(b[0]), "r"(b[1]));
}

__device__ __forceinline__ void ldmx4(unsigned& r0, unsigned& r1, unsigned& r2, unsigned& r3,
                                      unsigned addr) {
    asm volatile("ldmatrix.sync.aligned.m8n8.x4.shared.b16 {%0,%1,%2,%3}, [%4];\n"
        : "=r"(r0), "=r"(r1), "=r"(r2), "=r"(r3) : "r"(addr));
}

__device__ __forceinline__ void cp16(unsigned saddr, const void* gaddr) {
    asm volatile("cp.async.cg.shared.global [%0], [%1], 16;\n" :: "r"(saddr), "l"(gaddr));
}
__device__ __forceinline__ void cp_commit() { asm volatile("cp.async.commit_group;\n"); }
template<int N> __device__ __forceinline__ void cp_wait() {
    asm volatile("cp.async.wait_group %0;\n" :: "n"(N));
}
__device__ __forceinline__ unsigned pack2(float lo, float hi) {
    __half2 h = __floats2half2_rn(lo, hi);
    return *(unsigned*)&h;
}
__device__ __forceinline__ unsigned ex2_h2(unsigned s) {
    unsigned r;
    asm("ex2.approx.f16x2 %0, %1;" : "=r"(r) : "r"(s));
    return r;
}

// ---------------- fused init: fp32->fp16 (x, Wqkv, Wo) + RoPE table ----------------
#define N8_X   (M_*D_/8)
#define N8_WQ  (NQKV*D_/8)
#define N8_WO  (D_*D_/8)
#define N8_ALL (N8_X + N8_WQ + N8_WO)

__global__ void init_all_kernel(const float4* __restrict__ x,
                                const float4* __restrict__ wq,
                                const float4* __restrict__ wo)
{
    if (blockIdx.x < 256) {
        int i = blockIdx.x * 256 + threadIdx.x;
        int p = i & 31, posv = i >> 5;
        float freq = exp2f(-(float)p * (13.287712379549449f / 32.0f));
        float ang = (float)posv * freq;
        float sn, cs;
        sincosf(ang, &sn, &cs);
        g_rope[i] = make_float2(cs, sn);
    }
    __half* xh  = g_xh;
    __half* wqh = g_wqkvh;
    __half* woh = g_woh;
    for (int i = blockIdx.x * 256 + threadIdx.x; i < N8_ALL; i += gridDim.x * 256) {
        const float4* s; uint4* d; int j = i;
        if (j < N8_X)            { s = x  + 2*j;              d = (uint4*)xh  + j; }
        else if ((j -= N8_X) < N8_WQ) { s = wq + 2*j;         d = (uint4*)wqh + j; }
        else { j -= N8_WQ;         s = wo + 2*j;              d = (uint4*)woh + j; }
        float4 a = s[0], b = s[1];
        uint4 o;
        o.x = pack2(a.x, a.y); o.y = pack2(a.z, a.w);
        o.z = pack2(b.x, b.y); o.w = pack2(b.z, b.w);
        *d = o;
    }
}

// ============================================================
// fp16 GEMM (R12): block 128x128, BK=32 halves, 4-stage cp.async,
// 256 threads, 8 warps (2m x 4n), warp 64x32, ldmatrix.
// ============================================================
#define LDAH 40              // smem row stride (halves): 32 + 8 pad
#define STGH (128*LDAH)      // halves per stage per matrix = 5120
#define GST  4               // pipeline stages

__device__ __forceinline__ void gemm_load_stage(
    __half* Asb, __half* Bsb, const __half* A, const __half* W,
    int m0, int n0, int k0, int tid)
{
    int row = tid >> 1;
    int cp  = (tid & 1) * 2;    // chunks cp, cp+1 (of 4 per 64B row)
    unsigned sa = (unsigned)__cvta_generic_to_shared(Asb + row*LDAH + cp*8);
    unsigned sb = (unsigned)__cvta_generic_to_shared(Bsb + row*LDAH + cp*8);
    const __half* ga = A + (size_t)(m0 + row)*1024 + k0 + cp*8;
    const __half* gb = W + (size_t)(n0 + row)*1024 + k0 + cp*8;
    cp16(sa,      ga);
    cp16(sa + 16, ga + 8);
    cp16(sb,      gb);
    cp16(sb + 16, gb + 8);
}

// Q pre-scale: 1/sqrt(64) * log2(e) so attention can use raw exp2
#define QSCALE (0.125f * 1.4426950408889634f)

template<bool ROPE>
__global__ __launch_bounds__(256, 2)
void gemm_f16(const __half* __restrict__ A, const __half* __restrict__ W,
              const int* __restrict__ pos, float* __restrict__ Cout)
{
    extern __shared__ __half hsm[];
    __half* As = hsm;            // GST stages x 5120
    __half* Bs = hsm + GST*STGH;

    const int tid = threadIdx.x, lane = tid & 31, wrp = tid >> 5;
    const int wm = wrp >> 2, wn = wrp & 3;
    const int g  = lane >> 2, tg = lane & 3;
    const int m0 = blockIdx.y * 128, n0 = blockIdx.x * 128;

    const int a_off = (wm*64 + (lane & 15))*LDAH + ((lane >> 4) << 3);
    const int b_off = (wn*32 + (lane & 7) + ((lane & 16) >> 1))*LDAH + (lane & 8);
    const unsigned sa_base = (unsigned)__cvta_generic_to_shared(As) + a_off*2;
    const unsigned sb_base = (unsigned)__cvta_generic_to_shared(Bs) + b_off*2;

    float acc[4][4][4];
    #pragma unroll
    for (int i = 0; i < 4; i++)
        #pragma unroll
        for (int j = 0; j < 4; j++)
            #pragma unroll
            for (int k = 0; k < 4; k++) acc[i][j][k] = 0.f;

    #pragma unroll
    for (int li = 0; li < GST-1; li++) {
        gemm_load_stage(As + li*STGH, Bs + li*STGH, A, W, m0, n0, li*32, tid);
        cp_commit();
    }

    for (int kt = 0; kt < 32; kt++) {
        cp_wait<GST-2>();
        __syncthreads();
        if (kt + GST-1 < 32) {
            int s = (kt + GST-1) % GST;
            gemm_load_stage(As + s*STGH, Bs + s*STGH, A, W, m0, n0, (kt + GST-1)*32, tid);
        }
        cp_commit();

        const unsigned sa = sa_base + (kt % GST)*STGH*2;
        const unsigned sb = sb_base + (kt % GST)*STGH*2;
        #pragma unroll
        for (int ks = 0; ks < 2; ks++) {
            unsigned af[4][4], bf[4][2];
            #pragma unroll
            for (int mt = 0; mt < 4; mt++)
                ldmx4(af[mt][0], af[mt][1], af[mt][2], af[mt][3],
                      sa + (mt*16*LDAH + ks*16)*2);
            #pragma unroll
            for (int p = 0; p < 2; p++)
                ldmx4(bf[2*p][0], bf[2*p][1], bf[2*p+1][0], bf[2*p+1][1],
                      sb + (p*16*LDAH + ks*16)*2);
            #pragma unroll
            for (int mt = 0; mt < 4; mt++)
                #pragma unroll
                for (int nt = 0; nt < 4; nt++)
                    mma_f16(acc[mt][nt], af[mt], bf[nt]);
        }
    }

    // ---- epilogue ----
    if (ROPE) {
        const int baseN = n0 + wn*32;
        const int which = baseN >> 10;              // 0:Q 1:K 2:V
        const int h     = (baseN & 1023) >> 6;
        const int dd0   = baseN & 63;               // 0 or 32
        const float qs  = (which == 0) ? QSCALE : 1.0f;
        #pragma unroll
        for (int mt = 0; mt < 4; mt++) {
            int r0 = m0 + wm*64 + mt*16 + g;
            int r1 = r0 + 8;
            int b0i = r0 >> 11, s0 = r0 & 2047;
            int b1i = r1 >> 11, s1 = r1 & 2047;
            if (which == 2) {
                // transposed V: [bh][d][s]
                const size_t base0 = (size_t)(b0i*H_ + h)*DK_;
                const size_t base1 = (size_t)(b1i*H_ + h)*DK_;
                #pragma unroll
                for (int nt = 0; nt < 4; nt++) {
                    int dd = dd0 + nt*8 + 2*tg;
                    g_V[(base0 + dd    )*S_ + s0] = __float2half_rn(acc[mt][nt][0]);
                    g_V[(base0 + dd + 1)*S_ + s0] = __float2half_rn(acc[mt][nt][1]);
                    g_V[(base1 + dd    )*S_ + s1] = __float2half_rn(acc[mt][nt][2]);
                    g_V[(base1 + dd + 1)*S_ + s1] = __float2half_rn(acc[mt][nt][3]);
                }
            } else {
                __half* gq = (which == 0) ? g_Q : g_K;
                int p0 = pos[r0], p1 = pos[r1];
                __half* d0 = gq + ((size_t)((b0i*H_ + h)*S_ + s0))*DK_;
                __half* d1 = gq + ((size_t)((b1i*H_ + h)*S_ + s1))*DK_;
                #pragma unroll
                for (int nt = 0; nt < 4; nt++) {
                    int dd = dd0 + nt*8 + 2*tg;
                    int p  = dd >> 1;
                    float2 cs0 = g_rope[p0*32 + p];
                    float2 cs1 = g_rope[p1*32 + p];
                    float e0 = acc[mt][nt][0], o0 = acc[mt][nt][1];
                    float e1 = acc[mt][nt][2], o1 = acc[mt][nt][3];
                    *(unsigned*)(d0 + dd) = pack2(qs*(cs0.x*e0 - cs0.y*o0), qs*(cs0.y*e0 + cs0.x*o0));
                    *(unsigned*)(d1 + dd) = pack2(qs*(cs1.x*e1 - cs1.y*o1), qs*(cs1.y*e1 + cs1.x*o1));
                }
            }
        }
    } else {
        #pragma unroll
        for (int mt = 0; mt < 4; mt++) {
            int r0 = m0 + wm*64 + mt*16 + g;
            #pragma unroll
            for (int nt = 0; nt < 4; nt++) {
                int col = n0 + wn*32 + nt*8 + 2*tg;
                *(float2*)(Cout + (size_t)r0*1024 + col)     = make_float2(acc[mt][nt][0], acc[mt][nt][1]);
                *(float2*)(Cout + (size_t)(r0+8)*1024 + col) = make_float2(acc[mt][nt][2], acc[mt][nt][3]);
            }
        }
    }
}

// ============================================================
// Flash attention (R12 + 4-stage pipeline): fp16 mma, ldmatrix,
// log2 softmax via ex2.approx.f16x2, row-sum via ones-column mma.
// Block: 128 q-rows, 8 warps (16 rows each). Key tiles of 64.
// V in transposed [bh][d][s] layout -> plain ldmatrix B-fragments.
// ============================================================
#define ABM 128
#define ABN 64
#define KSH 72               // K/V smem row stride (halves)
#define KVSH (ABN*KSH)       // 4608 halves per matrix per stage
#define NSTG 4

__device__ __forceinline__ void load_kv(__half* Kd, __half* Vd,
    const __half* Kp, const __half* Vtp, int n0, int tid)
{
    int row = tid >> 2;           // 0..63
    int ch  = (tid & 3) * 2;      // chunks ch, ch+1 (of 8 per 128B row)
    const __half* kg = Kp  + (size_t)(n0 + row)*DK_ + ch*8;
    const __half* vg = Vtp + (size_t)row*S_ + n0 + ch*8;
    unsigned ks = (unsigned)__cvta_generic_to_shared(Kd + row*KSH + ch*8);
    unsigned vs = (unsigned)__cvta_generic_to_shared(Vd + row*KSH + ch*8);
    cp16(ks,      kg);
    cp16(ks + 16, kg + 8);
    cp16(vs,      vg);
    cp16(vs + 16, vg + 8);
}

__global__ __launch_bounds__(256, 2)
void attn_mma_kernel()
{
    extern __shared__ __half hsm[];   // NSTG stages x (K 4608 + V 4608) halves

    const int tid = threadIdx.x, lane = tid & 31, w = tid >> 5;
    const int g = lane >> 2, tg = lane & 3;
    const int bh = blockIdx.y;
    const int tile = (int)gridDim.x - 1 - (int)blockIdx.x;   // heavy tiles first
    const int m0 = tile * ABM;

    const __half* Qp  = g_Q + (size_t)bh * S_ * DK_;
    const __half* Kp  = g_K + (size_t)bh * S_ * DK_;
    const __half* Vtp = g_V + (size_t)bh * DK_ * S_;

    const int row0 = m0 + w*16 + g;
    const int row1 = row0 + 8;

    const int kv_off = ((lane & 7) + ((lane & 16) >> 1))*KSH + (lane & 8);
    const unsigned smem_base = (unsigned)__cvta_generic_to_shared(hsm) + kv_off*2;

    // ones-column B fragment for the row-sum mma: B[n][k] = (n==0)
    const unsigned ones_b = ((lane >> 2) == 0) ? 0x3C003C00u : 0u;
    unsigned ones_bb[2] = { ones_b, ones_b };

    // ---- Q fragments straight from gmem (one-time, pre-scaled) ----
    unsigned qa[4][4];
    {
        const __half* q0 = Qp + (size_t)row0*DK_ + 2*tg;
        const __half* q1 = Qp + (size_t)row1*DK_ + 2*tg;
        #pragma unroll
        for (int ks = 0; ks < 4; ks++) {
            qa[ks][0] = *(const unsigned*)(q0 + ks*16);
            qa[ks][1] = *(const unsigned*)(q1 + ks*16);
            qa[ks][2] = *(const unsigned*)(q0 + ks*16 + 8);
            qa[ks][3] = *(const unsigned*)(q1 + ks*16 + 8);
        }
    }

    float o[8][4];
    #pragma unroll
    for (int nt = 0; nt < 8; nt++)
        #pragma unroll
        for (int i = 0; i < 4; i++) o[nt][i] = 0.f;
    float osum[4] = {0.f, 0.f, 0.f, 0.f};     // row-sum accumulator (ones column)

    float mrow0 = -1e30f, mrow1 = -1e30f;
    const int fullT = m0 / ABN;
    const int nT = fullT + 2;

    // prologue: up to 3 stages in flight
    #pragma unroll
    for (int li = 0; li < NSTG-1; li++) {
        if (li < nT) {
            __half* st = hsm + li * 2 * KVSH;
            load_kv(st, st + KVSH, Kp, Vtp, li*ABN, tid);
        }
        cp_commit();
    }

    for (int t = 0; t < nT; t++) {
        cp_wait<NSTG-2>();
        __syncthreads();
        if (t + NSTG-1 < nT) {
            __half* st = hsm + ((t + NSTG-1) % NSTG) * 2 * KVSH;
            load_kv(st, st + KVSH, Kp, Vtp, (t + NSTG-1)*ABN, tid);
        }
        cp_commit();

        const unsigned Ksb = smem_base + ((t % NSTG) * 2 * KVSH)*2;
        const unsigned Vsb = Ksb + KVSH*2;
        const int n0 = t * ABN;

        // ---- scores: S = Q @ K^T  (log2-domain; scale folded into Q) ----
        float sc[8][4];
        #pragma unroll
        for (int nt = 0; nt < 8; nt++)
            #pragma unroll
            for (int i = 0; i < 4; i++) sc[nt][i] = 0.f;

        #pragma unroll
        for (int ks = 0; ks < 4; ks++) {
            #pragma unroll
            for (int p = 0; p < 4; p++) {
                unsigned bf[2][2];
                ldmx4(bf[0][0], bf[0][1], bf[1][0], bf[1][1],
                      Ksb + (p*16*KSH + ks*16)*2);
                mma_f16(sc[2*p],   qa[ks], bf[0]);
                mma_f16(sc[2*p+1], qa[ks], bf[1]);
            }
        }

        // causal mask (only the last two tiles touch the diagonal)
        if (t >= fullT) {
            #pragma unroll
            for (int nt = 0; nt < 8; nt++) {
                int c0 = n0 + nt*8 + 2*tg, c1 = c0 + 1;
                if (c0 > row0) sc[nt][0] = -1e30f;
                if (c1 > row0) sc[nt][1] = -1e30f;
                if (c0 > row1) sc[nt][2] = -1e30f;
                if (c1 > row1) sc[nt][3] = -1e30f;
            }
        }

        // ---- running max (log2 domain) ----
        float mx0 = -1e30f, mx1 = -1e30f;
        #pragma unroll
        for (int nt = 0; nt < 8; nt++) {
            mx0 = fmaxf(mx0, fmaxf(sc[nt][0], sc[nt][1]));
            mx1 = fmaxf(mx1, fmaxf(sc[nt][2], sc[nt][3]));
        }
        mx0 = fmaxf(mx0, __shfl_xor_sync(0xffffffffu, mx0, 1));
        mx0 = fmaxf(mx0, __shfl_xor_sync(0xffffffffu, mx0, 2));
        mx1 = fmaxf(mx1, __shfl_xor_sync(0xffffffffu, mx1, 1));
        mx1 = fmaxf(mx1, __shfl_xor_sync(0xffffffffu, mx1, 2));

        float mn0 = fmaxf(mrow0, mx0), mn1 = fmaxf(mrow1, mx1);
        float al0 = exp2f(mrow0 - mn0), al1 = exp2f(mrow1 - mn1);
        mrow0 = mn0; mrow1 = mn1;

        // ---- P = 2^(s-m) directly in packed fp16 (A-fragment layout) ----
        unsigned pP[4][4];
        #pragma unroll
        for (int ks = 0; ks < 4; ks++) {
            pP[ks][0] = ex2_h2(pack2(sc[2*ks  ][0] - mn0, sc[2*ks  ][1] - mn0));
            pP[ks][1] = ex2_h2(pack2(sc[2*ks  ][2] - mn1, sc[2*ks  ][3] - mn1));
            pP[ks][2] = ex2_h2(pack2(sc[2*ks+1][0] - mn0, sc[2*ks+1][1] - mn0));
            pP[ks][3] = ex2_h2(pack2(sc[2*ks+1][2] - mn1, sc[2*ks+1][3] - mn1));
        }

        // rescale O and row-sum accumulator
        #pragma unroll
        for (int nt = 0; nt < 8; nt++) {
            o[nt][0] *= al0; o[nt][1] *= al0;
            o[nt][2] *= al1; o[nt][3] *= al1;
        }
        osum[0] *= al0; osum[1] *= al0;
        osum[2] *= al1; osum[3] *= al1;

        // ---- PV + row-sum mma ----
        #pragma unroll
        for (int ks = 0; ks < 4; ks++) {
            mma_f16(osum, pP[ks], ones_bb);
            #pragma unroll
            for (int p = 0; p < 4; p++) {
                unsigned bf[2][2];
                ldmx4(bf[0][0], bf[0][1], bf[1][0], bf[1][1],
                      Vsb + (p*16*KSH + ks*16)*2);
                mma_f16(o[2*p],   pP[ks], bf[0]);
                mma_f16(o[2*p+1], pP[ks], bf[1]);
            }
        }
    }

    // ---- epilogue: recover l via shfl, normalize, write fp16 ----
    float l0 = __shfl_sync(0xffffffffu, osum[0], lane & ~3);
    float l1 = __shfl_sync(0xffffffffu, osum[2], lane & ~3);
    const float il0 = 1.0f / l0, il1 = 1.0f / l1;
    const int bb = bh >> 4, hh = bh & 15;
    __half* dst0 = g_attn + ((size_t)(bb*S_ + row0))*D_ + hh*DK_;
    __half* dst1 = g_attn + ((size_t)(bb*S_ + row1))*D_ + hh*DK_;
    #pragma unroll
    for (int nt = 0; nt < 8; nt++) {
        int d = nt*8 + 2*tg;
        *(unsigned*)(dst0 + d) = pack2(o[nt][0]*il0, o[nt][1]*il0);
        *(unsigned*)(dst1 + d) = pack2(o[nt][2]*il1, o[nt][3]*il1);
    }
}

// ============================================================
// Launch
// ============================================================
extern "C" void kernel_launch(void* const* d_in, const int* in_sizes, int n_in,
                              void* d_out, int out_size)
{
    const float* x    = (const float*)d_in[0];
    const int*   pos  = (const int*)  d_in[1];
    const float* wqkv = (const float*)d_in[2];
    const float* wo   = (const float*)d_in[3];
    float* out = (float*)d_out;

    (void)in_sizes; (void)n_in; (void)out_size;

    const int GEMM_SMEM = GST*STGH*2*(int)sizeof(__half);      // 81920
    const int ATTN_SMEM = NSTG*2*KVSH*(int)sizeof(__half);     // 73728
    cudaFuncSetAttribute((const void*)gemm_f16<true>,
                         cudaFuncAttributeMaxDynamicSharedMemorySize, GEMM_SMEM);
    cudaFuncSetAttribute((const void*)gemm_f16<false>,
                         cudaFuncAttributeMaxDynamicSharedMemorySize, GEMM_SMEM);
    cudaFuncSetAttribute((const void*)attn_mma_kernel,
                         cudaFuncAttributeMaxDynamicSharedMemorySize, ATTN_SMEM);

    __half* xh; __half* wqh; __half* woh; __half* ah;
    cudaGetSymbolAddress((void**)&xh,  g_xh);
    cudaGetSymbolAddress((void**)&wqh, g_wqkvh);
    cudaGetSymbolAddress((void**)&woh, g_woh);
    cudaGetSymbolAddress((void**)&ah,  g_attn);

    init_all_kernel<<<888, 256>>>((const float4*)x, (const float4*)wqkv, (const float4*)wo);

    gemm_f16<true ><<<dim3(NQKV/128, M_/128), 256, GEMM_SMEM>>>(xh, wqh, pos, nullptr);
    attn_mma_kernel<<<dim3(S_/ABM, B_*H_), 256, ATTN_SMEM>>>();
    gemm_f16<false><<<dim3(D_/128, M_/128), 256, GEMM_SMEM>>>(ah, woh, pos, out);
}